// round 15
// baseline (speedup 1.0000x reference)
#include <cuda_runtime.h>

#define BB 16
#define NN 4096
#define SS 1024
#define KK 24
#define DD 64
#define CC 67      // D+3
#define CO 131     // 2D+3
#define GG 16      // anchors per knn block
#define NCHUNK (SS/GG)

#define NEG_BIG -3.0e38f

typedef unsigned long long ull;
typedef unsigned int uint;

__device__ int    g_fps[BB*SS];
__device__ int    g_knn[BB*SS*KK];
__device__ double g_sum[BB];
__device__ double g_sumsq[BB];
__device__ float  g_scale[BB];
__device__ int    g_progress[BB];

__device__ __forceinline__ uint sortable(float f) {
    uint u = __float_as_uint(f);
    return u ^ (((int)u >> 31) | 0x80000000u);
}
__device__ __forceinline__ ull packf2(float lo, float hi) {
    ull r; asm("mov.b64 %0,{%1,%2};" : "=l"(r) : "f"(lo), "f"(hi)); return r;
}
__device__ __forceinline__ void unpackf2(ull v, float& lo, float& hi) {
    asm("mov.b64 {%0,%1},%2;" : "=f"(lo), "=f"(hi) : "l"(v));
}
__device__ __forceinline__ ull add2(ull a, ull b) {
    ull r; asm("add.rn.f32x2 %0,%1,%2;" : "=l"(r) : "l"(a), "l"(b)); return r;
}
__device__ __forceinline__ ull mul2(ull a, ull b) {
    ull r; asm("mul.rn.f32x2 %0,%1,%2;" : "=l"(r) : "l"(a), "l"(b)); return r;
}

// ---------------------------------------------------------------------------
__global__ void init_kernel()
{
    int t = threadIdx.x;
    if (t < BB) { g_progress[t] = 0; g_sum[t] = 0.0; g_sumsq[t] = 0.0; }
}

// ---------------------------------------------------------------------------
// Fused kernel. Blocks 0..15: FPS role. Blocks 16+: KNN role (chunk-major).
// Selection arithmetic bit-identical to passing R14.
// KNN selection: two-phase. Phase 1: each warp extracts its local top-24
// (iterative (key,idx) argmin over its 512 points; warp REDUX, no barriers).
// Phase 2: warp 0 merges 8x24 candidates by lexicographic min. Global top-24
// is contained in the union of per-warp top-24s, and lexicographic merge ==
// iterative global argmin with lowest-index ties => identical output.
// ---------------------------------------------------------------------------
__global__ void __launch_bounds__(256) fused_kernel(const float* __restrict__ xyz,
                                                    const float* __restrict__ points)
{
    extern __shared__ float sm[];
    float* sx = sm; float* sy = sm + NN; float* sz = sm + 2*NN;
    int t = threadIdx.x;
    int wid = t >> 5, lane = t & 31;

    if (blockIdx.x < BB) {
        // ================= FPS role =================
        __shared__ ull wwin[2][8];
        int b = blockIdx.x;
        const float* p = xyz + (size_t)b * NN * 3;
        for (int i = t; i < NN; i += 256) {
            sx[i] = p[3*i]; sy[i] = p[3*i+1]; sz[i] = p[3*i+2];
        }
        __syncthreads();

        ull pxx[8], pyy[8], pzz[8];
        float dist[16];
#pragma unroll
        for (int m = 0; m < 8; m++) {
            int i0 = t + (2*m)*256, i1 = t + (2*m+1)*256;
            pxx[m] = packf2(sx[i0], sx[i1]);
            pyy[m] = packf2(sy[i0], sy[i1]);
            pzz[m] = packf2(sz[i0], sz[i1]);
            dist[2*m] = 1e10f; dist[2*m+1] = 1e10f;
        }

        int last = 0;
        int parity = 0;
        for (int s = 0; s < SS; s++) {
            if (t == 0) {
                g_fps[b*SS + s] = last;
                if ((s & 15) == 15) {
                    __threadfence();
                    atomicExch(&g_progress[b], s + 1);
                }
            }
            float lx = sx[last], ly = sy[last], lz = sz[last];
            ull nlx2 = packf2(-lx, -lx);
            ull nly2 = packf2(-ly, -ly);
            ull nlz2 = packf2(-lz, -lz);

            float bv = NEG_BIG; int bi = 0;
#pragma unroll
            for (int m = 0; m < 8; m++) {
                ull dx = add2(pxx[m], nlx2);
                ull dy = add2(pyy[m], nly2);
                ull dz = add2(pzz[m], nlz2);
                dx = mul2(dx, dx); dy = mul2(dy, dy); dz = mul2(dz, dz);
                ull ss2 = add2(add2(dx, dy), dz);
                float d0, d1; unpackf2(ss2, d0, d1);
                float n0 = fminf(dist[2*m], d0);  dist[2*m] = n0;
                if (n0 > bv) { bv = n0; bi = t + (2*m)*256; }
                float n1 = fminf(dist[2*m+1], d1); dist[2*m+1] = n1;
                if (n1 > bv) { bv = n1; bi = t + (2*m+1)*256; }
            }
            uint mybits = __float_as_uint(bv);
            uint wbits = __reduce_max_sync(0xffffffffu, mybits);
            uint cand  = (mybits == wbits) ? (uint)bi : 0xffffffffu;
            uint widx  = __reduce_min_sync(0xffffffffu, cand);
            if (lane == 0)
                wwin[parity][wid] = ((ull)wbits << 32) | (ull)(0xffffffffu - widx);
            __syncthreads();
            ull wmax = wwin[parity][0];
#pragma unroll
            for (int w = 1; w < 8; w++) {
                ull o = wwin[parity][w];
                if (o > wmax) wmax = o;
            }
            parity ^= 1;
            last = (int)(0xffffffffu - (uint)wmax);
        }
        if (t == 0) { __threadfence(); atomicExch(&g_progress[b], SS); }
    } else {
        // ================= KNN role =================
        __shared__ ull s_cand[8*KK];   // per-warp top-24 candidates
        __shared__ int s_sel[KK];
        int kbid = blockIdx.x - BB;
        int chunk = kbid / BB;           // chunk-major
        int b     = kbid % BB;
        int s0    = chunk * GG;
        const bool useV1 = (b < 8);

        const float* p = xyz + (size_t)b * NN * 3;
        for (int i = t; i < NN; i += 256) {
            sx[i] = p[3*i]; sy[i] = p[3*i+1]; sz[i] = p[3*i+2];
        }
        // wait for this chunk's FPS indices (L2 load poll + sleep backoff)
        if (t == 0) {
            int need = s0 + GG;
            while (__ldcg(&g_progress[b]) < need) __nanosleep(512);
        }
        __syncthreads();

        double lsum = 0.0, lsq = 0.0;
        const float* pf = points + (size_t)b * NN * DD;

        for (int g = 0; g < GG; g++) {
            int s = s0 + g;
            int aidx = __ldcg(&g_fps[b*SS + s]);
            float ax = sx[aidx], ay = sy[aidx], az = sz[aidx];
            float s2;
            if (useV1) s2 = __fmaf_rn(az, az, __fmaf_rn(ay, ay, __fmul_rn(ax, ax)));
            else       s2 = __fadd_rn(__fadd_rn(__fmul_rn(ax,ax), __fmul_rn(ay,ay)),
                                      __fmul_rn(az,az));
            uint kb[16];
            uint mb = 0xffffffffu; int mj = 0;
#pragma unroll
            for (int j = 0; j < 16; j++) {
                int i = t + j*256;
                float qx = sx[i], qy = sy[i], qz = sz[i];
                float d2;
                if (useV1) d2 = __fmaf_rn(qz, qz, __fmaf_rn(qy, qy, __fmul_rn(qx, qx)));
                else       d2 = __fadd_rn(__fadd_rn(__fmul_rn(qx,qx), __fmul_rn(qy,qy)),
                                          __fmul_rn(qz,qz));
                float cr = __fmaf_rn(az, qz, __fmaf_rn(ay, qy, __fmul_rn(ax, qx)));
                float dv = __fsub_rn(__fadd_rn(s2, d2), __fmul_rn(2.0f, cr));
                uint sk = sortable(dv);
                kb[j] = sk;
                if (sk < mb) { mb = sk; mj = j; }    // strict < keeps lowest idx
            }

            // Phase 1: per-warp top-24 (no block barriers)
            for (int k = 0; k < KK; k++) {
                uint wbits = __reduce_min_sync(0xffffffffu, mb);
                uint cand  = (mb == wbits) ? (uint)(t + mj*256) : 0xffffffffu;
                uint wi    = __reduce_min_sync(0xffffffffu, cand);
                if (lane == 0) s_cand[wid*KK + k] = ((ull)wbits << 32) | (ull)wi;
                if (mb == wbits && (uint)(t + mj*256) == wi) {
                    kb[mj] = 0xffffffffu;
                    mb = 0xffffffffu; mj = 0;
#pragma unroll
                    for (int j = 0; j < 16; j++)
                        if (kb[j] < mb) { mb = kb[j]; mj = j; }
                }
            }
            __syncthreads();   // s_cand complete

            // Phase 2: warp 0 merges 192 candidates lexicographically
            if (wid == 0) {
                ull ent[6];
                uint used = 0;
#pragma unroll
                for (int q = 0; q < 6; q++) ent[q] = s_cand[lane + 32*q];
                for (int k = 0; k < KK; k++) {
                    ull lm = 0xffffffffffffffffull;
                    int lq = -1;
#pragma unroll
                    for (int q = 0; q < 6; q++)
                        if (!((used >> q) & 1) && ent[q] < lm) { lm = ent[q]; lq = q; }
                    uint hb = (uint)(lm >> 32);
                    uint wb = __reduce_min_sync(0xffffffffu, hb);
                    uint cand = (hb == wb) ? (uint)lm : 0xffffffffu;
                    uint wi = __reduce_min_sync(0xffffffffu, cand);
                    if (hb == wb && (uint)lm == wi && lq >= 0) used |= (1u << lq);
                    if (lane == 0) {
                        s_sel[k] = (int)wi;
                        g_knn[((size_t)b*SS + s)*KK + k] = (int)wi;
                    }
                }
            }
            __syncthreads();   // s_sel visible

            float fsum = 0.0f, fsq = 0.0f;
            for (int e = t; e < KK*CC; e += 256) {
                int k = e / CC;
                int c = e - k*CC;
                int ni = s_sel[k];
                float gv, mv;
                if (c < DD) {
                    gv = pf[(size_t)ni*DD + c];
                    mv = pf[(size_t)aidx*DD + c];
                } else {
                    int cc = c - DD;
                    gv = (cc == 0) ? sx[ni]   : ((cc == 1) ? sy[ni]   : sz[ni]);
                    mv = (cc == 0) ? sx[aidx] : ((cc == 1) ? sy[aidx] : sz[aidx]);
                }
                float df = __fsub_rn(gv, mv);
                fsum += df;
                fsq  = __fmaf_rn(df, df, fsq);
            }
            lsum += (double)fsum;
            lsq  += (double)fsq;
        }

#pragma unroll
        for (int off = 16; off; off >>= 1) {
            lsum += __shfl_down_sync(0xffffffffu, lsum, off);
            lsq  += __shfl_down_sync(0xffffffffu, lsq,  off);
        }
        __shared__ double dsm[8], dsq[8];
        if (lane == 0) { dsm[wid] = lsum; dsq[wid] = lsq; }
        __syncthreads();
        if (t == 0) {
            double a = 0.0, c = 0.0;
            for (int i = 0; i < 8; i++) { a += dsm[i]; c += dsq[i]; }
            atomicAdd(&g_sum[b], a);
            atomicAdd(&g_sumsq[b], c);
        }
    }
}

// ---------------------------------------------------------------------------
__global__ void std_kernel()
{
    int b = threadIdx.x;
    if (b < BB) {
        double n    = (double)SS * KK * CC;
        double mean = g_sum[b] / n;
        double var  = (g_sumsq[b] - g_sum[b] * mean) / (n - 1.0);
        if (var < 0.0) var = 0.0;
        float sd = (float)sqrt(var);
        g_scale[b] = 1.0f / (sd + 1e-5f);
    }
}

// ---------------------------------------------------------------------------
// Output writer: one block per (b,s); 786 float4 stores, fully coalesced.
// ---------------------------------------------------------------------------
__global__ void __launch_bounds__(256) out_kernel(const float* __restrict__ xyz,
                                                  const float* __restrict__ points,
                                                  const float* __restrict__ alpha,
                                                  const float* __restrict__ beta,
                                                  float* __restrict__ out_xyz,
                                                  float* __restrict__ out_pts)
{
    int bs = blockIdx.x;
    int b  = bs / SS;
    int t  = threadIdx.x;

    __shared__ float s_anchor[CC];
    __shared__ float s_al[CC];
    __shared__ float s_be[CC];
    __shared__ int   s_ni[KK];
    __shared__ float s_sc;

    int aidx = g_fps[bs];
    if (t < KK) s_ni[t] = g_knn[(size_t)bs*KK + t];
    if (t < DD) s_anchor[t] = points[((size_t)b*NN + aidx)*DD + t];
    else if (t < CC) s_anchor[t] = xyz[((size_t)b*NN + aidx)*3 + (t - DD)];
    if (t >= 128 && t < 128 + CC) {
        s_al[t-128] = alpha[t-128];
        s_be[t-128] = beta[t-128];
    }
    if (t == CC) s_sc = g_scale[b];
    __syncthreads();

    float sc = s_sc;
    float4* o4 = reinterpret_cast<float4*>(out_pts + (size_t)bs * KK * CO);

    for (int v = t; v < (KK*CO)/4; v += 256) {
        int e = v * 4;
        int k = e / CO;
        int c = e - k * CO;
        float comps[4];
#pragma unroll
        for (int q = 0; q < 4; q++) {
            float val;
            if (c < CC) {
                int ni = s_ni[k];
                float gv;
                if (c < DD) gv = __ldg(&points[((size_t)b*NN + ni)*DD + c]);
                else        gv = __ldg(&xyz[((size_t)b*NN + ni)*3 + (c - DD)]);
                float df = __fsub_rn(gv, s_anchor[c]);
                float nm = __fmul_rn(df, sc);
                val = __fadd_rn(__fmul_rn(s_al[c], nm), s_be[c]);
            } else {
                val = s_anchor[c - CC];
            }
            comps[q] = val;
            if (++c == CO) { c = 0; k++; }
        }
        o4[v] = make_float4(comps[0], comps[1], comps[2], comps[3]);
    }
    if (out_xyz != nullptr && t < 3) {
        out_xyz[(size_t)bs*3 + t] = s_anchor[DD + t];
    }
}

// ---------------------------------------------------------------------------
extern "C" void kernel_launch(void* const* d_in, const int* in_sizes, int n_in,
                              void* d_out, int out_size)
{
    const float* xyz    = (const float*)d_in[0];
    const float* points = (const float*)d_in[1];
    const float* alpha  = (const float*)d_in[2];
    const float* beta   = (const float*)d_in[3];
    float* out = (float*)d_out;

    float* out_xyz;
    float* out_pts;
    if (out_size >= BB*SS*3 + BB*SS*KK*CO) {
        out_xyz = out;
        out_pts = out + (size_t)BB*SS*3;
    } else {
        out_xyz = nullptr;
        out_pts = out;
    }

    size_t shmem = (size_t)3 * NN * sizeof(float);
    cudaFuncSetAttribute(fused_kernel, cudaFuncAttributeMaxDynamicSharedMemorySize, (int)shmem);

    init_kernel<<<1, 32>>>();
    fused_kernel<<<BB + BB*NCHUNK, 256, shmem>>>(xyz, points);
    std_kernel<<<1, 32>>>();
    out_kernel<<<BB*SS, 256>>>(xyz, points, alpha, beta, out_xyz, out_pts);
}

// round 16
// speedup vs baseline: 1.0348x; 1.0348x over previous
#include <cuda_runtime.h>

#define BB 16
#define NN 4096
#define SS 1024
#define KK 24
#define DD 64
#define CC 67      // D+3
#define CO 131     // 2D+3
#define GG 16      // anchors per chunk
#define CPB 4      // chunks per knn block
#define KNB (BB * (SS/GG) / CPB)   // 256 knn blocks

#define NEG_BIG -3.0e38f

typedef unsigned long long ull;
typedef unsigned int uint;

__device__ int    g_fps[BB*SS];
__device__ int    g_knn[BB*SS*KK];
__device__ double g_sum[BB];
__device__ double g_sumsq[BB];
__device__ float  g_scale[BB];
__device__ int    g_progress[BB];

__device__ __forceinline__ uint sortable(float f) {
    uint u = __float_as_uint(f);
    return u ^ (((int)u >> 31) | 0x80000000u);
}
__device__ __forceinline__ ull packf2(float lo, float hi) {
    ull r; asm("mov.b64 %0,{%1,%2};" : "=l"(r) : "f"(lo), "f"(hi)); return r;
}
__device__ __forceinline__ void unpackf2(ull v, float& lo, float& hi) {
    asm("mov.b64 {%0,%1},%2;" : "=f"(lo), "=f"(hi) : "l"(v));
}
__device__ __forceinline__ ull add2(ull a, ull b) {
    ull r; asm("add.rn.f32x2 %0,%1,%2;" : "=l"(r) : "l"(a), "l"(b)); return r;
}
__device__ __forceinline__ ull mul2(ull a, ull b) {
    ull r; asm("mul.rn.f32x2 %0,%1,%2;" : "=l"(r) : "l"(a), "l"(b)); return r;
}

// ---------------------------------------------------------------------------
__global__ void init_kernel()
{
    int t = threadIdx.x;
    if (t < BB) { g_progress[t] = 0; g_sum[t] = 0.0; g_sumsq[t] = 0.0; }
}

// ---------------------------------------------------------------------------
// Fused kernel, 110KB dynamic smem (uses 48KB) -> 2 blocks/SM; grid 272 =
// all blocks wave-1 resident. Blocks 0..15: FPS. Blocks 16..271: KNN, each
// handling 4 chunks {cg, cg+16, cg+32, cg+48} of one batch in ascending order.
// Selection arithmetic bit-identical to passing R14.
// ---------------------------------------------------------------------------
__global__ void __launch_bounds__(256) fused_kernel(const float* __restrict__ xyz,
                                                    const float* __restrict__ points)
{
    extern __shared__ float sm[];
    float* sx = sm; float* sy = sm + NN; float* sz = sm + 2*NN;
    int t = threadIdx.x;
    int wid = t >> 5, lane = t & 31;

    __shared__ ull wwin[2][8];

    if (blockIdx.x < BB) {
        // ================= FPS role =================
        int b = blockIdx.x;
        const float* p = xyz + (size_t)b * NN * 3;
        for (int i = t; i < NN; i += 256) {
            sx[i] = p[3*i]; sy[i] = p[3*i+1]; sz[i] = p[3*i+2];
        }
        __syncthreads();

        ull pxx[8], pyy[8], pzz[8];
        float dist[16];
#pragma unroll
        for (int m = 0; m < 8; m++) {
            int i0 = t + (2*m)*256, i1 = t + (2*m+1)*256;
            pxx[m] = packf2(sx[i0], sx[i1]);
            pyy[m] = packf2(sy[i0], sy[i1]);
            pzz[m] = packf2(sz[i0], sz[i1]);
            dist[2*m] = 1e10f; dist[2*m+1] = 1e10f;
        }

        int last = 0;
        int parity = 0;
        for (int s = 0; s < SS; s++) {
            if (t == 0) {
                g_fps[b*SS + s] = last;
                if ((s & 15) == 15) {
                    __threadfence();
                    atomicExch(&g_progress[b], s + 1);
                }
            }
            float lx = sx[last], ly = sy[last], lz = sz[last];
            ull nlx2 = packf2(-lx, -lx);
            ull nly2 = packf2(-ly, -ly);
            ull nlz2 = packf2(-lz, -lz);

            float bv = NEG_BIG; int bi = 0;
#pragma unroll
            for (int m = 0; m < 8; m++) {
                ull dx = add2(pxx[m], nlx2);        // per-lane rn(px - lx)
                ull dy = add2(pyy[m], nly2);
                ull dz = add2(pzz[m], nlz2);
                dx = mul2(dx, dx); dy = mul2(dy, dy); dz = mul2(dz, dz);
                ull ss2 = add2(add2(dx, dy), dz);   // rn(rn(dx2+dy2)+dz2)
                float d0, d1; unpackf2(ss2, d0, d1);
                float n0 = fminf(dist[2*m], d0);  dist[2*m] = n0;
                if (n0 > bv) { bv = n0; bi = t + (2*m)*256; }
                float n1 = fminf(dist[2*m+1], d1); dist[2*m+1] = n1;
                if (n1 > bv) { bv = n1; bi = t + (2*m+1)*256; }
            }
            uint mybits = __float_as_uint(bv);
            uint wbits = __reduce_max_sync(0xffffffffu, mybits);
            uint cand  = (mybits == wbits) ? (uint)bi : 0xffffffffu;
            uint widx  = __reduce_min_sync(0xffffffffu, cand);
            if (lane == 0)
                wwin[parity][wid] = ((ull)wbits << 32) | (ull)(0xffffffffu - widx);
            __syncthreads();
            ull wmax = wwin[parity][0];
#pragma unroll
            for (int w = 1; w < 8; w++) {
                ull o = wwin[parity][w];
                if (o > wmax) wmax = o;
            }
            parity ^= 1;
            last = (int)(0xffffffffu - (uint)wmax);
        }
        if (t == 0) { __threadfence(); atomicExch(&g_progress[b], SS); }
    } else {
        // ================= KNN role =================
        int kbid = blockIdx.x - BB;
        int b    = kbid % BB;
        int cg   = kbid / BB;            // 0..15
        const bool useV1 = (b < 8);

        const float* p = xyz + (size_t)b * NN * 3;
        for (int i = t; i < NN; i += 256) {
            sx[i] = p[3*i]; sy[i] = p[3*i+1]; sz[i] = p[3*i+2];
        }
        __syncthreads();

        __shared__ int s_sel[KK];
        double lsum = 0.0, lsq = 0.0;
        const float* pf = points + (size_t)b * NN * DD;
        int parity = 0;

        for (int cc4 = 0; cc4 < CPB; cc4++) {
            int chunk = cg + cc4 * 16;   // ascending: pipelines with FPS
            int s0 = chunk * GG;
            // wait for this chunk's FPS indices (plain load poll + backoff)
            if (t == 0) {
                int need = s0 + GG;
                while (__ldcg(&g_progress[b]) < need) __nanosleep(128);
            }
            __syncthreads();

            for (int g = 0; g < GG; g++) {
                int s = s0 + g;
                int aidx = __ldcg(&g_fps[b*SS + s]);
                float ax = sx[aidx], ay = sy[aidx], az = sz[aidx];
                float s2;
                if (useV1) s2 = __fmaf_rn(az, az, __fmaf_rn(ay, ay, __fmul_rn(ax, ax)));
                else       s2 = __fadd_rn(__fadd_rn(__fmul_rn(ax,ax), __fmul_rn(ay,ay)),
                                          __fmul_rn(az,az));
                uint kb[16];
                uint mb = 0xffffffffu; int mj = 0;
#pragma unroll
                for (int j = 0; j < 16; j++) {
                    int i = t + j*256;
                    float qx = sx[i], qy = sy[i], qz = sz[i];
                    float d2;
                    if (useV1) d2 = __fmaf_rn(qz, qz, __fmaf_rn(qy, qy, __fmul_rn(qx, qx)));
                    else       d2 = __fadd_rn(__fadd_rn(__fmul_rn(qx,qx), __fmul_rn(qy,qy)),
                                              __fmul_rn(qz,qz));
                    float cr = __fmaf_rn(az, qz, __fmaf_rn(ay, qy, __fmul_rn(ax, qx)));
                    float dv = __fsub_rn(__fadd_rn(s2, d2), __fmul_rn(2.0f, cr));
                    uint sk = sortable(dv);
                    kb[j] = sk;
                    if (sk < mb) { mb = sk; mj = j; }   // strict < keeps lowest idx
                }

                for (int k = 0; k < KK; k++) {
                    uint wbits = __reduce_min_sync(0xffffffffu, mb);
                    uint cand  = (mb == wbits) ? (uint)(t + mj*256) : 0xffffffffu;
                    uint wi    = __reduce_min_sync(0xffffffffu, cand);
                    if (lane == 0) wwin[parity][wid] = ((ull)wbits << 32) | (ull)wi;
                    __syncthreads();
                    ull wmin = wwin[parity][0];
#pragma unroll
                    for (int w = 1; w < 8; w++) {
                        ull o = wwin[parity][w];
                        if (o < wmin) wmin = o;
                    }
                    parity ^= 1;
                    int widx = (int)(uint)wmin;
                    if (t == 0) {
                        s_sel[k] = widx;
                        g_knn[((size_t)b*SS + s)*KK + k] = widx;
                    }
                    if ((widx & 255) == t) {
                        kb[widx >> 8] = 0xffffffffu;
                        mb = 0xffffffffu; mj = 0;
#pragma unroll
                        for (int j = 0; j < 16; j++)
                            if (kb[j] < mb) { mb = kb[j]; mj = j; }
                    }
                }
                __syncthreads();   // s_sel visible for stats

                float fsum = 0.0f, fsq = 0.0f;
                for (int e = t; e < KK*CC; e += 256) {
                    int k = e / CC;
                    int c = e - k*CC;
                    int ni = s_sel[k];
                    float gv, mv;
                    if (c < DD) {
                        gv = pf[(size_t)ni*DD + c];
                        mv = pf[(size_t)aidx*DD + c];
                    } else {
                        int c2 = c - DD;
                        gv = (c2 == 0) ? sx[ni]   : ((c2 == 1) ? sy[ni]   : sz[ni]);
                        mv = (c2 == 0) ? sx[aidx] : ((c2 == 1) ? sy[aidx] : sz[aidx]);
                    }
                    float df = __fsub_rn(gv, mv);
                    fsum += df;
                    fsq  = __fmaf_rn(df, df, fsq);
                }
                lsum += (double)fsum;
                lsq  += (double)fsq;
            }
        }

#pragma unroll
        for (int off = 16; off; off >>= 1) {
            lsum += __shfl_down_sync(0xffffffffu, lsum, off);
            lsq  += __shfl_down_sync(0xffffffffu, lsq,  off);
        }
        __shared__ double dsm[8], dsq[8];
        if (lane == 0) { dsm[wid] = lsum; dsq[wid] = lsq; }
        __syncthreads();
        if (t == 0) {
            double a = 0.0, c = 0.0;
            for (int i = 0; i < 8; i++) { a += dsm[i]; c += dsq[i]; }
            atomicAdd(&g_sum[b], a);
            atomicAdd(&g_sumsq[b], c);
        }
    }
}

// ---------------------------------------------------------------------------
__global__ void std_kernel()
{
    int b = threadIdx.x;
    if (b < BB) {
        double n    = (double)SS * KK * CC;
        double mean = g_sum[b] / n;
        double var  = (g_sumsq[b] - g_sum[b] * mean) / (n - 1.0);
        if (var < 0.0) var = 0.0;
        float sd = (float)sqrt(var);
        g_scale[b] = 1.0f / (sd + 1e-5f);
    }
}

// ---------------------------------------------------------------------------
// Output writer: one block per (b,s). Neighbor rows staged in smem with
// coalesced loads (kills gather replays), then 786 float4 streaming stores.
// ---------------------------------------------------------------------------
__global__ void __launch_bounds__(256) out_kernel(const float* __restrict__ xyz,
                                                  const float* __restrict__ points,
                                                  const float* __restrict__ alpha,
                                                  const float* __restrict__ beta,
                                                  float* __restrict__ out_xyz,
                                                  float* __restrict__ out_pts)
{
    int bs = blockIdx.x;
    int b  = bs / SS;
    int t  = threadIdx.x;

    __shared__ float s_rows[KK][68];   // 67 used, padded
    __shared__ float s_anchor[CC];
    __shared__ float s_al[CC];
    __shared__ float s_be[CC];
    __shared__ int   s_ni[KK];
    __shared__ float s_sc;

    int aidx = g_fps[bs];
    if (t < KK) s_ni[t] = g_knn[(size_t)bs*KK + t];
    if (t < DD) s_anchor[t] = points[((size_t)b*NN + aidx)*DD + t];
    else if (t < CC) s_anchor[t] = xyz[((size_t)b*NN + aidx)*3 + (t - DD)];
    if (t >= 128 && t < 128 + CC) {
        s_al[t-128] = alpha[t-128];
        s_be[t-128] = beta[t-128];
    }
    if (t == CC) s_sc = g_scale[b];
    __syncthreads();

    // stage neighbor rows, coalesced per row
    for (int e = t; e < KK*68; e += 256) {
        int k = e / 68;
        int c = e - k*68;
        int ni = s_ni[k];
        float v = 0.0f;
        if (c < DD)      v = points[((size_t)b*NN + ni)*DD + c];
        else if (c < CC) v = xyz[((size_t)b*NN + ni)*3 + (c - DD)];
        s_rows[k][c] = v;
    }
    __syncthreads();

    float sc = s_sc;
    float4* o4 = reinterpret_cast<float4*>(out_pts + (size_t)bs * KK * CO);

    for (int v = t; v < (KK*CO)/4; v += 256) {
        int e = v * 4;
        int k = e / CO;
        int c = e - k * CO;
        float comps[4];
#pragma unroll
        for (int q = 0; q < 4; q++) {
            float val;
            if (c < CC) {
                float df = __fsub_rn(s_rows[k][c], s_anchor[c]);
                float nm = __fmul_rn(df, sc);
                val = __fadd_rn(__fmul_rn(s_al[c], nm), s_be[c]);
            } else {
                val = s_anchor[c - CC];
            }
            comps[q] = val;
            if (++c == CO) { c = 0; k++; }
        }
        o4[v] = make_float4(comps[0], comps[1], comps[2], comps[3]);
    }
    if (out_xyz != nullptr && t < 3) {
        out_xyz[(size_t)bs*3 + t] = s_anchor[DD + t];
    }
}

// ---------------------------------------------------------------------------
extern "C" void kernel_launch(void* const* d_in, const int* in_sizes, int n_in,
                              void* d_out, int out_size)
{
    const float* xyz    = (const float*)d_in[0];
    const float* points = (const float*)d_in[1];
    const float* alpha  = (const float*)d_in[2];
    const float* beta   = (const float*)d_in[3];
    float* out = (float*)d_out;

    float* out_xyz;
    float* out_pts;
    if (out_size >= BB*SS*3 + BB*SS*KK*CO) {
        out_xyz = out;
        out_pts = out + (size_t)BB*SS*3;
    } else {
        out_xyz = nullptr;
        out_pts = out;
    }

    // 110KB dynamic smem (only 48KB indexed) caps occupancy at 2 blocks/SM,
    // so all 272 blocks are wave-1 resident and FPS shares with <=1 knn block.
    size_t shmem = 110 * 1024;
    cudaFuncSetAttribute(fused_kernel, cudaFuncAttributeMaxDynamicSharedMemorySize, (int)shmem);

    init_kernel<<<1, 32>>>();
    fused_kernel<<<BB + KNB, 256, shmem>>>(xyz, points);
    std_kernel<<<1, 32>>>();
    out_kernel<<<BB*SS, 256>>>(xyz, points, alpha, beta, out_xyz, out_pts);
}

// round 17
// speedup vs baseline: 1.0671x; 1.0312x over previous
#include <cuda_runtime.h>

#define BB 16
#define NN 4096
#define SS 1024
#define KK 24
#define DD 64
#define CC 67      // D+3
#define CO 131     // 2D+3
#define GG 16      // anchors per chunk
#define CPB 2      // chunks per knn block
#define KNB (BB * (SS/GG) / CPB)   // 512 knn blocks

#define NEG_BIG -3.0e38f

typedef unsigned long long ull;
typedef unsigned int uint;

__device__ int    g_fps[BB*SS];
__device__ int    g_knn[BB*SS*KK];
__device__ double g_sum[BB];
__device__ double g_sumsq[BB];
__device__ float  g_scale[BB];
__device__ int    g_progress[BB];

__device__ __forceinline__ uint sortable(float f) {
    uint u = __float_as_uint(f);
    return u ^ (((int)u >> 31) | 0x80000000u);
}
__device__ __forceinline__ ull packf2(float lo, float hi) {
    ull r; asm("mov.b64 %0,{%1,%2};" : "=l"(r) : "f"(lo), "f"(hi)); return r;
}
__device__ __forceinline__ void unpackf2(ull v, float& lo, float& hi) {
    asm("mov.b64 {%0,%1},%2;" : "=f"(lo), "=f"(hi) : "l"(v));
}
__device__ __forceinline__ ull add2(ull a, ull b) {
    ull r; asm("add.rn.f32x2 %0,%1,%2;" : "=l"(r) : "l"(a), "l"(b)); return r;
}
__device__ __forceinline__ ull mul2(ull a, ull b) {
    ull r; asm("mul.rn.f32x2 %0,%1,%2;" : "=l"(r) : "l"(a), "l"(b)); return r;
}

// ---------------------------------------------------------------------------
__global__ void init_kernel()
{
    int t = threadIdx.x;
    if (t < BB) { g_progress[t] = 0; g_sum[t] = 0.0; g_sumsq[t] = 0.0; }
}

// ---------------------------------------------------------------------------
// Fused kernel. 528 blocks total at 4 blocks/SM = single wave (all resident).
// Blocks 0..15: FPS role. Blocks 16..527: KNN role, 2 chunks each (cg, cg+32)
// ascending so gating pipelines with the FPS stream.
// Selection arithmetic bit-identical to passing R14 (759us).
// ---------------------------------------------------------------------------
__global__ void __launch_bounds__(256) fused_kernel(const float* __restrict__ xyz,
                                                    const float* __restrict__ points)
{
    extern __shared__ float sm[];
    float* sx = sm; float* sy = sm + NN; float* sz = sm + 2*NN;
    int t = threadIdx.x;
    int wid = t >> 5, lane = t & 31;

    __shared__ ull wwin[2][8];

    if (blockIdx.x < BB) {
        // ================= FPS role =================
        int b = blockIdx.x;
        const float* p = xyz + (size_t)b * NN * 3;
        for (int i = t; i < NN; i += 256) {
            sx[i] = p[3*i]; sy[i] = p[3*i+1]; sz[i] = p[3*i+2];
        }
        __syncthreads();

        ull pxx[8], pyy[8], pzz[8];
        float dist[16];
#pragma unroll
        for (int m = 0; m < 8; m++) {
            int i0 = t + (2*m)*256, i1 = t + (2*m+1)*256;
            pxx[m] = packf2(sx[i0], sx[i1]);
            pyy[m] = packf2(sy[i0], sy[i1]);
            pzz[m] = packf2(sz[i0], sz[i1]);
            dist[2*m] = 1e10f; dist[2*m+1] = 1e10f;
        }

        int last = 0;
        int parity = 0;
        for (int s = 0; s < SS; s++) {
            if (t == 0) {
                g_fps[b*SS + s] = last;
                if ((s & 15) == 15) {
                    __threadfence();
                    atomicExch(&g_progress[b], s + 1);
                }
            }
            float lx = sx[last], ly = sy[last], lz = sz[last];
            ull nlx2 = packf2(-lx, -lx);
            ull nly2 = packf2(-ly, -ly);
            ull nlz2 = packf2(-lz, -lz);

            float bv = NEG_BIG; int bi = 0;
#pragma unroll
            for (int m = 0; m < 8; m++) {
                ull dx = add2(pxx[m], nlx2);        // per-lane rn(px - lx)
                ull dy = add2(pyy[m], nly2);
                ull dz = add2(pzz[m], nlz2);
                dx = mul2(dx, dx); dy = mul2(dy, dy); dz = mul2(dz, dz);
                ull ss2 = add2(add2(dx, dy), dz);   // rn(rn(dx2+dy2)+dz2)
                float d0, d1; unpackf2(ss2, d0, d1);
                float n0 = fminf(dist[2*m], d0);  dist[2*m] = n0;
                if (n0 > bv) { bv = n0; bi = t + (2*m)*256; }
                float n1 = fminf(dist[2*m+1], d1); dist[2*m+1] = n1;
                if (n1 > bv) { bv = n1; bi = t + (2*m+1)*256; }
            }
            uint mybits = __float_as_uint(bv);
            uint wbits = __reduce_max_sync(0xffffffffu, mybits);
            uint cand  = (mybits == wbits) ? (uint)bi : 0xffffffffu;
            uint widx  = __reduce_min_sync(0xffffffffu, cand);
            if (lane == 0)
                wwin[parity][wid] = ((ull)wbits << 32) | (ull)(0xffffffffu - widx);
            __syncthreads();
            ull wmax = wwin[parity][0];
#pragma unroll
            for (int w = 1; w < 8; w++) {
                ull o = wwin[parity][w];
                if (o > wmax) wmax = o;
            }
            parity ^= 1;
            last = (int)(0xffffffffu - (uint)wmax);
        }
        if (t == 0) { __threadfence(); atomicExch(&g_progress[b], SS); }
    } else {
        // ================= KNN role =================
        int kbid = blockIdx.x - BB;
        int b    = kbid % BB;
        int cg   = kbid / BB;            // 0..31
        const bool useV1 = (b < 8);

        const float* p = xyz + (size_t)b * NN * 3;
        for (int i = t; i < NN; i += 256) {
            sx[i] = p[3*i]; sy[i] = p[3*i+1]; sz[i] = p[3*i+2];
        }
        __syncthreads();

        __shared__ int s_sel[KK];
        double lsum = 0.0, lsq = 0.0;
        const float* pf = points + (size_t)b * NN * DD;
        int parity = 0;

        for (int cc4 = 0; cc4 < CPB; cc4++) {
            int chunk = cg + cc4 * 32;   // ascending: pipelines with FPS
            int s0 = chunk * GG;
            if (t == 0) {
                int need = s0 + GG;
                while (__ldcg(&g_progress[b]) < need) __nanosleep(256);
            }
            __syncthreads();

            for (int g = 0; g < GG; g++) {
                int s = s0 + g;
                int aidx = __ldcg(&g_fps[b*SS + s]);
                float ax = sx[aidx], ay = sy[aidx], az = sz[aidx];
                float s2;
                if (useV1) s2 = __fmaf_rn(az, az, __fmaf_rn(ay, ay, __fmul_rn(ax, ax)));
                else       s2 = __fadd_rn(__fadd_rn(__fmul_rn(ax,ax), __fmul_rn(ay,ay)),
                                          __fmul_rn(az,az));
                uint kb[16];
                uint mb = 0xffffffffu; int mj = 0;
#pragma unroll
                for (int j = 0; j < 16; j++) {
                    int i = t + j*256;
                    float qx = sx[i], qy = sy[i], qz = sz[i];
                    float d2;
                    if (useV1) d2 = __fmaf_rn(qz, qz, __fmaf_rn(qy, qy, __fmul_rn(qx, qx)));
                    else       d2 = __fadd_rn(__fadd_rn(__fmul_rn(qx,qx), __fmul_rn(qy,qy)),
                                              __fmul_rn(qz,qz));
                    float cr = __fmaf_rn(az, qz, __fmaf_rn(ay, qy, __fmul_rn(ax, qx)));
                    float dv = __fsub_rn(__fadd_rn(s2, d2), __fmul_rn(2.0f, cr));
                    uint sk = sortable(dv);
                    kb[j] = sk;
                    if (sk < mb) { mb = sk; mj = j; }   // strict < keeps lowest idx
                }

                for (int k = 0; k < KK; k++) {
                    uint wbits = __reduce_min_sync(0xffffffffu, mb);
                    uint cand  = (mb == wbits) ? (uint)(t + mj*256) : 0xffffffffu;
                    uint wi    = __reduce_min_sync(0xffffffffu, cand);
                    if (lane == 0) wwin[parity][wid] = ((ull)wbits << 32) | (ull)wi;
                    __syncthreads();
                    ull wmin = wwin[parity][0];
#pragma unroll
                    for (int w = 1; w < 8; w++) {
                        ull o = wwin[parity][w];
                        if (o < wmin) wmin = o;
                    }
                    parity ^= 1;
                    int widx = (int)(uint)wmin;
                    if (t == 0) {
                        s_sel[k] = widx;
                        g_knn[((size_t)b*SS + s)*KK + k] = widx;
                    }
                    if ((widx & 255) == t) {
                        kb[widx >> 8] = 0xffffffffu;
                        mb = 0xffffffffu; mj = 0;
#pragma unroll
                        for (int j = 0; j < 16; j++)
                            if (kb[j] < mb) { mb = kb[j]; mj = j; }
                    }
                }
                __syncthreads();   // s_sel visible for stats

                float fsum = 0.0f, fsq = 0.0f;
                for (int e = t; e < KK*CC; e += 256) {
                    int k = e / CC;
                    int c = e - k*CC;
                    int ni = s_sel[k];
                    float gv, mv;
                    if (c < DD) {
                        gv = pf[(size_t)ni*DD + c];
                        mv = pf[(size_t)aidx*DD + c];
                    } else {
                        int c2 = c - DD;
                        gv = (c2 == 0) ? sx[ni]   : ((c2 == 1) ? sy[ni]   : sz[ni]);
                        mv = (c2 == 0) ? sx[aidx] : ((c2 == 1) ? sy[aidx] : sz[aidx]);
                    }
                    float df = __fsub_rn(gv, mv);
                    fsum += df;
                    fsq  = __fmaf_rn(df, df, fsq);
                }
                lsum += (double)fsum;
                lsq  += (double)fsq;
            }
        }

#pragma unroll
        for (int off = 16; off; off >>= 1) {
            lsum += __shfl_down_sync(0xffffffffu, lsum, off);
            lsq  += __shfl_down_sync(0xffffffffu, lsq,  off);
        }
        __shared__ double dsm[8], dsq[8];
        if (lane == 0) { dsm[wid] = lsum; dsq[wid] = lsq; }
        __syncthreads();
        if (t == 0) {
            double a = 0.0, c = 0.0;
            for (int i = 0; i < 8; i++) { a += dsm[i]; c += dsq[i]; }
            atomicAdd(&g_sum[b], a);
            atomicAdd(&g_sumsq[b], c);
        }
    }
}

// ---------------------------------------------------------------------------
__global__ void std_kernel()
{
    int b = threadIdx.x;
    if (b < BB) {
        double n    = (double)SS * KK * CC;
        double mean = g_sum[b] / n;
        double var  = (g_sumsq[b] - g_sum[b] * mean) / (n - 1.0);
        if (var < 0.0) var = 0.0;
        float sd = (float)sqrt(var);
        g_scale[b] = 1.0f / (sd + 1e-5f);
    }
}

// ---------------------------------------------------------------------------
// Output writer: one block per (b,s). Three phases:
//  A: normalized channels (24x67) with cheap const-div index math -> smem
//  B: anchor-rep channels (24x64) copied from smem anchor -> smem
//  C: stream 786 aligned float4 stores (12576B per row-block, 16B aligned)
// ---------------------------------------------------------------------------
__global__ void __launch_bounds__(256) out_kernel(const float* __restrict__ xyz,
                                                  const float* __restrict__ points,
                                                  const float* __restrict__ alpha,
                                                  const float* __restrict__ beta,
                                                  float* __restrict__ out_xyz,
                                                  float* __restrict__ out_pts)
{
    int bs = blockIdx.x;
    int b  = bs / SS;
    int t  = threadIdx.x;

    __shared__ float s_out[KK*CO];     // 3144 floats = 12.6KB
    __shared__ float s_anchor[CC];
    __shared__ float s_al[CC];
    __shared__ float s_be[CC];
    __shared__ int   s_ni[KK];
    __shared__ float s_sc;

    int aidx = g_fps[bs];
    if (t < KK) s_ni[t] = g_knn[(size_t)bs*KK + t];
    if (t < DD) s_anchor[t] = points[((size_t)b*NN + aidx)*DD + t];
    else if (t < CC) s_anchor[t] = xyz[((size_t)b*NN + aidx)*3 + (t - DD)];
    if (t >= 128 && t < 128 + CC) {
        s_al[t-128] = alpha[t-128];
        s_be[t-128] = beta[t-128];
    }
    if (t == CC) s_sc = g_scale[b];
    __syncthreads();

    float sc = s_sc;

    // Phase A: normalized channels
    for (int e = t; e < KK*CC; e += 256) {
        int k = e / CC;           // const division -> mul/shift
        int c = e - k*CC;
        int ni = s_ni[k];
        float gv;
        if (c < DD) gv = __ldg(&points[((size_t)b*NN + ni)*DD + c]);
        else        gv = __ldg(&xyz[((size_t)b*NN + ni)*3 + (c - DD)]);
        float df = __fsub_rn(gv, s_anchor[c]);
        float nm = __fmul_rn(df, sc);
        s_out[k*CO + c] = __fadd_rn(__fmul_rn(s_al[c], nm), s_be[c]);
    }
    // Phase B: anchor-rep channels (c in [67,131) = anchor feature c-67)
    for (int e = t; e < KK*DD; e += 256) {
        int k = e >> 6;           // /64
        int c = e & 63;
        s_out[k*CO + CC + c] = s_anchor[c];
    }
    __syncthreads();

    // Phase C: aligned float4 stream out
    float4* o4 = reinterpret_cast<float4*>(out_pts + (size_t)bs * KK * CO);
    const float4* i4 = reinterpret_cast<const float4*>(s_out);
    for (int v = t; v < (KK*CO)/4; v += 256)
        o4[v] = i4[v];

    if (out_xyz != nullptr && t < 3) {
        out_xyz[(size_t)bs*3 + t] = s_anchor[DD + t];
    }
}

// ---------------------------------------------------------------------------
extern "C" void kernel_launch(void* const* d_in, const int* in_sizes, int n_in,
                              void* d_out, int out_size)
{
    const float* xyz    = (const float*)d_in[0];
    const float* points = (const float*)d_in[1];
    const float* alpha  = (const float*)d_in[2];
    const float* beta   = (const float*)d_in[3];
    float* out = (float*)d_out;

    float* out_xyz;
    float* out_pts;
    if (out_size >= BB*SS*3 + BB*SS*KK*CO) {
        out_xyz = out;
        out_pts = out + (size_t)BB*SS*3;
    } else {
        out_xyz = nullptr;
        out_pts = out;
    }

    size_t shmem = (size_t)3 * NN * sizeof(float);
    cudaFuncSetAttribute(fused_kernel, cudaFuncAttributeMaxDynamicSharedMemorySize, (int)shmem);

    init_kernel<<<1, 32>>>();
    fused_kernel<<<BB + KNB, 256, shmem>>>(xyz, points);
    std_kernel<<<1, 32>>>();
    out_kernel<<<BB*SS, 256>>>(xyz, points, alpha, beta, out_xyz, out_pts);
}